// round 4
// baseline (speedup 1.0000x reference)
#include <cuda_runtime.h>
#include <cuda_bf16.h>
#include <math.h>
#include <stdint.h>

#define B_ 2
#define S_ 2048
#define E_ 512
#define H_ 8
#define DH_ 64
#define SCALE_ 0.125f  // 64^-0.5

#define BK 16          // fp32-equiv k per mainloop iter (projection GEMMs)
#define SK 40          // proj smem row stride (16 hi + 16 lo + 8 pad)
#define SKA 136        // attn Q/K/V row stride (64 hi | 64 lo | 8 pad) = 272B
#define SKP 264        // attn P row stride (128 hi | 128 lo | 8 pad) = 528B

typedef __nv_bfloat16 bf16;
typedef __nv_bfloat162 bf162;

// ---- scratch (device globals; allocation is forbidden) ----
__device__ bf16 g_qin_hi[4096 * 512], g_qin_lo[4096 * 512];
__device__ bf16 g_kin_hi[4096 * 512], g_kin_lo[4096 * 512];
__device__ bf16 g_vin_hi[4096 * 512], g_vin_lo[4096 * 512];
__device__ bf16 g_Wq_hi[512 * 512], g_Wq_lo[512 * 512];
__device__ bf16 g_Wk_hi[512 * 512], g_Wk_lo[512 * 512];
__device__ bf16 g_Wv_hi[512 * 512], g_Wv_lo[512 * 512];
__device__ bf16 g_Wo_hi[512 * 512], g_Wo_lo[512 * 512];
__device__ bf16 g_Q_hi[16 * 2048 * 64], g_Q_lo[16 * 2048 * 64];    // [bh][s][d]
__device__ bf16 g_K_hi[16 * 2048 * 64], g_K_lo[16 * 2048 * 64];    // [bh][s][d]
__device__ bf16 g_Vt_hi[16 * 64 * 2048], g_Vt_lo[16 * 64 * 2048];  // [bh][d][s]
__device__ bf16 g_C_hi[4096 * 512], g_C_lo[4096 * 512];            // ctx [m][e]
__device__ float g_tw[S_ * S_];

// ---------------------------------------------------------------------------
__global__ void tw_kernel(const float* __restrict__ ld) {
    int i = blockIdx.x * blockDim.x + threadIdx.x;
    float4 v = ((const float4*)ld)[i];
    float4 o = make_float4(__expf(-v.x), __expf(-v.y), __expf(-v.z), __expf(-v.w));
    ((float4*)g_tw)[i] = o;
}

__global__ void split_kernel(const float* __restrict__ src, bf16* __restrict__ hi,
                             bf16* __restrict__ lo, int n4) {
    int i = blockIdx.x * blockDim.x + threadIdx.x;
    if (i >= n4) return;
    float4 v = ((const float4*)src)[i];
    bf16 h0 = __float2bfloat16(v.x), h1 = __float2bfloat16(v.y);
    bf16 h2 = __float2bfloat16(v.z), h3 = __float2bfloat16(v.w);
    ((bf162*)hi)[2 * i]     = __halves2bfloat162(h0, h1);
    ((bf162*)hi)[2 * i + 1] = __halves2bfloat162(h2, h3);
    ((bf162*)lo)[2 * i] = __halves2bfloat162(
        __float2bfloat16(v.x - __bfloat162float(h0)),
        __float2bfloat16(v.y - __bfloat162float(h1)));
    ((bf162*)lo)[2 * i + 1] = __halves2bfloat162(
        __float2bfloat16(v.z - __bfloat162float(h2)),
        __float2bfloat16(v.w - __bfloat162float(h3)));
}

// ---------------------------------------------------------------------------
__device__ __forceinline__ void ldsm4(uint32_t addr, uint32_t& r0, uint32_t& r1,
                                      uint32_t& r2, uint32_t& r3) {
    asm volatile("ldmatrix.sync.aligned.m8n8.x4.shared.b16 {%0,%1,%2,%3}, [%4];"
                 : "=r"(r0), "=r"(r1), "=r"(r2), "=r"(r3) : "r"(addr));
}

__device__ __forceinline__ void mma16816(float* c, const uint32_t* a, const uint32_t* b) {
    asm volatile(
        "mma.sync.aligned.m16n8k16.row.col.f32.bf16.bf16.f32 "
        "{%0,%1,%2,%3}, {%4,%5,%6,%7}, {%8,%9}, {%0,%1,%2,%3};\n"
        : "+f"(c[0]), "+f"(c[1]), "+f"(c[2]), "+f"(c[3])
        : "r"(a[0]), "r"(a[1]), "r"(a[2]), "r"(a[3]), "r"(b[0]), "r"(b[1]));
}

__device__ __forceinline__ void cpa16(uint32_t dst, const void* src) {
    asm volatile("cp.async.cg.shared.global [%0], [%1], 16;" :: "r"(dst), "l"(src));
}
__device__ __forceinline__ void cp_commit() { asm volatile("cp.async.commit_group;"); }
template <int N>
__device__ __forceinline__ void cp_wait() { asm volatile("cp.async.wait_group %0;" :: "n"(N)); }

// projection-GEMM stage loader: [ROWS x 16] hi+lo tile, row layout [hi16|lo16|pad8]
template <int ROWS>
__device__ __forceinline__ void stage_load(const bf16* __restrict__ hi,
                                           const bf16* __restrict__ lo,
                                           int lda, int k0, uint32_t sdst, int tid) {
    #pragma unroll
    for (int i = 0; i < ROWS * 4 / 256; i++) {
        int idx = tid + i * 256;
        int r = idx >> 2, c = idx & 3;
        const bf16* src = ((c < 2) ? hi : lo) + (size_t)r * lda + k0 + (c & 1) * 8;
        uint32_t dst = sdst + (r * SK + ((c < 2) ? 0 : 16) + (c & 1) * 8) * 2;
        cpa16(dst, src);
    }
}

// attention loader: [ROWS x 64] hi+lo, row layout [hi64|lo64|pad8], stride SKA
template <int ROWS>
__device__ __forceinline__ void load64t(const bf16* __restrict__ hi,
                                        const bf16* __restrict__ lo,
                                        int lda, uint32_t sdst, int tid) {
    #pragma unroll
    for (int i = 0; i < ROWS * 16 / 256; i++) {
        int idx = tid + i * 256;
        int r = idx >> 4, c = idx & 15;
        const bf16* src = ((c < 8) ? hi : lo) + (size_t)r * lda + (c & 7) * 8;
        uint32_t dst = sdst + (r * SKA + ((c < 8) ? 0 : 64) + (c & 7) * 8) * 2;
        cpa16(dst, src);
    }
}

// Vt tile loader: two arrays [64 x 128] (hi then lo) at stride SKA
__device__ __forceinline__ void loadVt(const bf16* __restrict__ vh,
                                       const bf16* __restrict__ vl,
                                       int kt, uint32_t sdst, int tid) {
    #pragma unroll
    for (int i = 0; i < 8; i++) {
        int idx = tid + i * 256;
        int a = idx >> 10, r = (idx >> 4) & 63, c = idx & 15;
        const bf16* src = (a ? vl : vh) + (size_t)r * S_ + kt * 128 + c * 8;
        uint32_t dst = sdst + (a * 64 * SKA + r * SKA + c * 8) * 2;
        cpa16(dst, src);
    }
}

// ---------------------------------------------------------------------------
// Projection / output GEMM: D = A . B^T in 3xBF16, double-buffered cp.async.
// MODE 0: split head layout [bh][s][d] (+bias)   MODE 3: split transposed [bh][d][s]
// MODE 1: fp32 [M,512] (+bias)
// ---------------------------------------------------------------------------
template <int WARPS_M, int WARPS_N, int BM, int BN, int MODE>
__global__ __launch_bounds__(256) void k_mm(
    const bf16* __restrict__ Ahi, const bf16* __restrict__ Alo,
    const bf16* __restrict__ Bhi, const bf16* __restrict__ Blo,
    const float* __restrict__ bias, float* __restrict__ out,
    bf16* __restrict__ outHi, bf16* __restrict__ outLo, int K) {
    constexpr int WM = BM / WARPS_M;
    constexpr int WN = BN / WARPS_N;
    constexpr int MF = WM / 16;
    constexpr int NF = WN / 8;
    constexpr int STAGE = (BM + BN) * SK;

    __shared__ bf16 smem[2 * STAGE];

    const int tid = threadIdx.x, wid = tid >> 5, lane = tid & 31;
    const int wm = wid % WARPS_M, wn = wid / WARPS_M;
    const int m0 = blockIdx.y * BM, n0 = blockIdx.x * BN;

    const bf16* Ahp = Ahi + (size_t)m0 * K;
    const bf16* Alp = Alo + (size_t)m0 * K;
    const bf16* Bhp = Bhi + (size_t)n0 * K;
    const bf16* Blp = Blo + (size_t)n0 * K;

    float acc[MF][NF][4];
    #pragma unroll
    for (int i = 0; i < MF; i++)
        #pragma unroll
        for (int j = 0; j < NF; j++)
            #pragma unroll
            for (int q = 0; q < 4; q++) acc[i][j][q] = 0.f;

    const uint32_t sbase = (uint32_t)__cvta_generic_to_shared(smem);
    const int t8 = lane >> 3, r8 = lane & 7;
    const int frow = r8 + 8 * (t8 & 1);
    const int fcol = 8 * (t8 >> 1);

    const int niter = K / BK;
    stage_load<BM>(Ahp, Alp, K, 0, sbase, tid);
    stage_load<BN>(Bhp, Blp, K, 0, sbase + BM * SK * 2, tid);
    cp_commit();

    for (int it = 0; it < niter; it++) {
        if (it + 1 < niter) {
            uint32_t sd = sbase + ((it + 1) & 1) * STAGE * 2;
            stage_load<BM>(Ahp, Alp, K, (it + 1) * BK, sd, tid);
            stage_load<BN>(Bhp, Blp, K, (it + 1) * BK, sd + BM * SK * 2, tid);
            cp_commit();
            cp_wait<1>();
        } else {
            cp_wait<0>();
        }
        __syncthreads();

        const uint32_t sA = sbase + (it & 1) * STAGE * 2;
        const uint32_t sB = sA + BM * SK * 2;
        #pragma unroll
        for (int p = 0; p < 3; p++) {
            const int ao = (p == 2) ? 16 : 0;
            const int bo = (p == 1) ? 16 : 0;
            uint32_t af[MF][4], bf[NF][2];
            #pragma unroll
            for (int mf = 0; mf < MF; mf++) {
                uint32_t addr = sA + ((wm * WM + mf * 16 + frow) * SK + ao + fcol) * 2;
                ldsm4(addr, af[mf][0], af[mf][1], af[mf][2], af[mf][3]);
            }
            #pragma unroll
            for (int nf2 = 0; nf2 < NF / 2; nf2++) {
                uint32_t r0, r1, r2, r3;
                uint32_t addr = sB + ((wn * WN + nf2 * 16 + frow) * SK + bo + fcol) * 2;
                ldsm4(addr, r0, r1, r2, r3);
                bf[2 * nf2][0] = r0;      bf[2 * nf2][1] = r2;
                bf[2 * nf2 + 1][0] = r1;  bf[2 * nf2 + 1][1] = r3;
            }
            #pragma unroll
            for (int mf = 0; mf < MF; mf++)
                #pragma unroll
                for (int nf = 0; nf < NF; nf++)
                    mma16816(acc[mf][nf], af[mf], bf[nf]);
        }
        __syncthreads();
    }

    const int lrow = lane >> 2, lcol = (lane & 3) * 2;
    #pragma unroll
    for (int mf = 0; mf < MF; mf++) {
        #pragma unroll
        for (int nf = 0; nf < NF; nf++) {
            #pragma unroll
            for (int hh = 0; hh < 2; hh++) {
                int m = m0 + wm * WM + mf * 16 + lrow + hh * 8;
                int n = n0 + wn * WN + nf * 8 + lcol;
                float v0 = acc[mf][nf][2 * hh];
                float v1 = acc[mf][nf][2 * hh + 1];
                if (MODE == 0) {
                    int b = m >> 11, s = m & 2047;
                    int h = n >> 6, d = n & 63;
                    size_t o = (((size_t)(b * H_ + h) * S_ + s) << 6) + d;
                    float x0 = v0 + bias[n], x1 = v1 + bias[n + 1];
                    bf16 h0 = __float2bfloat16(x0), h1 = __float2bfloat16(x1);
                    *(bf162*)&outHi[o] = __halves2bfloat162(h0, h1);
                    *(bf162*)&outLo[o] = __halves2bfloat162(
                        __float2bfloat16(x0 - __bfloat162float(h0)),
                        __float2bfloat16(x1 - __bfloat162float(h1)));
                } else if (MODE == 3) {
                    int b = m >> 11, s = m & 2047;
                    int h = n >> 6, d = n & 63;
                    size_t base = (size_t)(b * H_ + h) * DH_;
                    float x0 = v0 + bias[n], x1 = v1 + bias[n + 1];
                    bf16 h0 = __float2bfloat16(x0), h1 = __float2bfloat16(x1);
                    outHi[(base + d) * S_ + s] = h0;
                    outHi[(base + d + 1) * S_ + s] = h1;
                    outLo[(base + d) * S_ + s] = __float2bfloat16(x0 - __bfloat162float(h0));
                    outLo[(base + d + 1) * S_ + s] = __float2bfloat16(x1 - __bfloat162float(h1));
                } else {  // MODE 1
                    float2 val = make_float2(v0 + bias[n], v1 + bias[n + 1]);
                    *(float2*)&out[(size_t)m * 512 + n] = val;
                }
            }
        }
    }
}

// ---------------------------------------------------------------------------
// Fused scores + softmax + P.V.  grid (S/128, B*H), 256 threads, 8 warps.
// Each warp owns 16 query rows (row-softmax stats warp-local).
// ---------------------------------------------------------------------------
__global__ __launch_bounds__(256) void fused_attn_kernel(
    const int* __restrict__ mask, const float* __restrict__ tbias,
    float* __restrict__ P) {
    extern __shared__ char smraw[];
    bf16* sPp = (bf16*)smraw;
    float* sm_m    = (float*)(smraw + 137216);
    float* sm_linv = sm_m + 128;

    const int tid = threadIdx.x, wid = tid >> 5, lane = tid & 31;
    const int bz = blockIdx.y;
    const int b = bz >> 3, h = bz & 7;
    const int m0 = blockIdx.x * 128;

    const bf16* Qh = g_Q_hi + ((size_t)bz * S_ + m0) * DH_;
    const bf16* Ql = g_Q_lo + ((size_t)bz * S_ + m0) * DH_;
    const bf16* Kh0 = g_K_hi + (size_t)bz * S_ * DH_;
    const bf16* Kl0 = g_K_lo + (size_t)bz * S_ * DH_;
    const bf16* Vh0 = g_Vt_hi + (size_t)bz * DH_ * S_;
    const bf16* Vl0 = g_Vt_lo + (size_t)bz * DH_ * S_;
    float* Pbh = P + (size_t)bz * S_ * S_;

    const uint32_t sbase = (uint32_t)__cvta_generic_to_shared(smraw);
    const uint32_t uQ = sbase;
    const uint32_t uK = sbase + 128 * SKA * 2;
    const uint32_t uP = sbase;
    const uint32_t uV = sbase + 128 * SKP * 2;

    const int t8 = lane >> 3, r8 = lane & 7;
    const int frow = r8 + 8 * (t8 & 1), fcol = 8 * (t8 >> 1);
    const int lrow = lane >> 2, lcol = (lane & 3) * 2;
    const float tb = tbias[h];

    // ---------------- pass 1: scores + online (m, l) ----------------
    load64t<128>(Qh, Ql, DH_, uQ, tid);
    load64t<128>(Kh0, Kl0, DH_, uK, tid);
    cp_commit();

    float m_r[2] = {-INFINITY, -INFINITY};
    float l_r[2] = {0.f, 0.f};

    for (int kt = 0; kt < 16; kt++) {
        if (kt + 1 < 16) {
            uint32_t dst = uK + ((kt + 1) & 1) * (128 * SKA * 2);
            load64t<128>(Kh0 + (size_t)(kt + 1) * 128 * DH_,
                         Kl0 + (size_t)(kt + 1) * 128 * DH_, DH_, dst, tid);
            cp_commit(); cp_wait<1>();
        } else cp_wait<0>();
        __syncthreads();

        float acc[16][4];
        #pragma unroll
        for (int j = 0; j < 16; j++)
            #pragma unroll
            for (int q = 0; q < 4; q++) acc[j][q] = 0.f;

        const uint32_t sKt = uK + (kt & 1) * (128 * SKA * 2);
        #pragma unroll
        for (int p = 0; p < 3; p++) {
            const int ao = (p == 2) ? 64 : 0;
            const int bo = (p == 1) ? 64 : 0;
            #pragma unroll
            for (int ks = 0; ks < 64; ks += 16) {
                uint32_t af[4], bf[16][2];
                ldsm4(uQ + ((wid * 16 + frow) * SKA + ao + ks + fcol) * 2,
                      af[0], af[1], af[2], af[3]);
                #pragma unroll
                for (int nf2 = 0; nf2 < 8; nf2++) {
                    uint32_t r0, r1, r2, r3;
                    ldsm4(sKt + ((nf2 * 16 + frow) * SKA + bo + ks + fcol) * 2,
                          r0, r1, r2, r3);
                    bf[2 * nf2][0] = r0;      bf[2 * nf2][1] = r2;
                    bf[2 * nf2 + 1][0] = r1;  bf[2 * nf2 + 1][1] = r3;
                }
                #pragma unroll
                for (int nf = 0; nf < 16; nf++) mma16816(acc[nf], af, bf[nf]);
            }
        }
        __syncthreads();

        // epilogue: scale + temporal bias + mask, write raw s, online stats
        #pragma unroll
        for (int nf = 0; nf < 16; nf++) {
            int n = kt * 128 + nf * 8 + lcol;
            #pragma unroll
            for (int hh = 0; hh < 2; hh++) {
                int m = m0 + wid * 16 + lrow + hh * 8;
                size_t mn = (size_t)m * S_ + n;
                float2 tw = *(const float2*)&g_tw[mn];
                int2 mk = *(const int2*)&mask[mn];
                float x0 = acc[nf][2 * hh] * SCALE_ + tb * tw.x;
                float x1 = acc[nf][2 * hh + 1] * SCALE_ + tb * tw.y;
                if (mk.x == 0) x0 = -1e9f;
                if (mk.y == 0) x1 = -1e9f;
                *(float2*)&Pbh[mn] = make_float2(x0, x1);
                acc[nf][2 * hh] = x0;
                acc[nf][2 * hh + 1] = x1;
            }
        }
        #pragma unroll
        for (int hh = 0; hh < 2; hh++) {
            float tmax = -INFINITY;
            #pragma unroll
            for (int nf = 0; nf < 16; nf++)
                tmax = fmaxf(tmax, fmaxf(acc[nf][2 * hh], acc[nf][2 * hh + 1]));
            tmax = fmaxf(tmax, __shfl_xor_sync(0xffffffffu, tmax, 1));
            tmax = fmaxf(tmax, __shfl_xor_sync(0xffffffffu, tmax, 2));
            float nm = fmaxf(m_r[hh], tmax);
            float ts = 0.f;
            #pragma unroll
            for (int nf = 0; nf < 16; nf++)
                ts += __expf(acc[nf][2 * hh] - nm) + __expf(acc[nf][2 * hh + 1] - nm);
            ts += __shfl_xor_sync(0xffffffffu, ts, 1);
            ts += __shfl_xor_sync(0xffffffffu, ts, 2);
            l_r[hh] = l_r[hh] * __expf(m_r[hh] - nm) + ts;
            m_r[hh] = nm;
        }
        __syncthreads();
    }

    if ((lane & 3) == 0) {
        sm_m[wid * 16 + lrow] = m_r[0];
        sm_m[wid * 16 + lrow + 8] = m_r[1];
        sm_linv[wid * 16 + lrow] = 1.0f / l_r[0];
        sm_linv[wid * 16 + lrow + 8] = 1.0f / l_r[1];
    }
    __syncthreads();

    // ---------------- pass 2: finalize P, accumulate O = P.V ----------------
    loadVt(Vh0, Vl0, 0, uV, tid);
    cp_commit();

    float acco[8][4];
    #pragma unroll
    for (int j = 0; j < 8; j++)
        #pragma unroll
        for (int q = 0; q < 4; q++) acco[j][q] = 0.f;

    for (int kt = 0; kt < 16; kt++) {
        if (kt + 1 < 16) {
            loadVt(Vh0, Vl0, kt + 1, uV + ((kt + 1) & 1) * (2 * 64 * SKA * 2), tid);
            cp_commit();
        }
        // read raw s (L2 / own writes), finalize, write P, split into smem
        #pragma unroll
        for (int nf = 0; nf < 16; nf++) {
            int nl = nf * 8 + lcol;
            int n = kt * 128 + nl;
            #pragma unroll
            for (int hh = 0; hh < 2; hh++) {
                int rl = wid * 16 + lrow + hh * 8;
                int m = m0 + rl;
                size_t mn = (size_t)m * S_ + n;
                float2 s = *(const float2*)&Pbh[mn];
                float mm = sm_m[rl], li = sm_linv[rl];
                float p0 = __expf(s.x - mm) * li;
                float p1 = __expf(s.y - mm) * li;
                *(float2*)&Pbh[mn] = make_float2(p0, p1);
                bf16 h0 = __float2bfloat16(p0), h1 = __float2bfloat16(p1);
                *(bf162*)&sPp[rl * SKP + nl] = __halves2bfloat162(h0, h1);
                *(bf162*)&sPp[rl * SKP + 128 + nl] = __halves2bfloat162(
                    __float2bfloat16(p0 - __bfloat162float(h0)),
                    __float2bfloat16(p1 - __bfloat162float(h1)));
            }
        }
        if (kt + 1 < 16) cp_wait<1>(); else cp_wait<0>();
        __syncthreads();

        const uint32_t sVt = uV + (kt & 1) * (2 * 64 * SKA * 2);
        #pragma unroll
        for (int p = 0; p < 3; p++) {
            const int ao = (p == 2) ? 128 : 0;
            const uint32_t vsel = sVt + ((p == 1) ? 64 * SKA * 2 : 0);
            #pragma unroll
            for (int ks = 0; ks < 8; ks++) {
                uint32_t af[4], bf[8][2];
                ldsm4(uP + ((wid * 16 + frow) * SKP + ao + ks * 16 + fcol) * 2,
                      af[0], af[1], af[2], af[3]);
                #pragma unroll
                for (int nf2 = 0; nf2 < 4; nf2++) {
                    uint32_t r0, r1, r2, r3;
                    ldsm4(vsel + ((nf2 * 16 + frow) * SKA + ks * 16 + fcol) * 2,
                          r0, r1, r2, r3);
                    bf[2 * nf2][0] = r0;      bf[2 * nf2][1] = r2;
                    bf[2 * nf2 + 1][0] = r1;  bf[2 * nf2 + 1][1] = r3;
                }
                #pragma unroll
                for (int nf = 0; nf < 8; nf++) mma16816(acco[nf], af, bf[nf]);
            }
        }
        __syncthreads();
    }

    // epilogue: write split ctx [b][m][h*64+d]
    #pragma unroll
    for (int nf = 0; nf < 8; nf++) {
        #pragma unroll
        for (int hh = 0; hh < 2; hh++) {
            int m = m0 + wid * 16 + lrow + hh * 8;
            int d = nf * 8 + lcol;
            size_t o = ((size_t)b * S_ + m) * E_ + h * DH_ + d;
            float v0 = acco[nf][2 * hh], v1 = acco[nf][2 * hh + 1];
            bf16 h0 = __float2bfloat16(v0), h1 = __float2bfloat16(v1);
            *(bf162*)&g_C_hi[o] = __halves2bfloat162(h0, h1);
            *(bf162*)&g_C_lo[o] = __halves2bfloat162(
                __float2bfloat16(v0 - __bfloat162float(h0)),
                __float2bfloat16(v1 - __bfloat162float(h1)));
        }
    }
}

// ---------------------------------------------------------------------------
#define SYM(p, s) cudaGetSymbolAddress((void**)&p, s)

extern "C" void kernel_launch(void* const* d_in, const int* in_sizes, int n_in,
                              void* d_out, int out_size) {
    const float* query = (const float*)d_in[0];
    const float* key   = (const float*)d_in[1];
    const float* value = (const float*)d_in[2];
    const int*   tmask = (const int*)d_in[3];
    const float* ldist = (const float*)d_in[4];
    const float* Wq = (const float*)d_in[5];
    const float* bq = (const float*)d_in[6];
    const float* Wk = (const float*)d_in[7];
    const float* bk = (const float*)d_in[8];
    const float* Wv = (const float*)d_in[9];
    const float* bv = (const float*)d_in[10];
    const float* Wo = (const float*)d_in[11];
    const float* bo = (const float*)d_in[12];
    const float* tbias = (const float*)d_in[13];

    float* out_attn  = (float*)d_out;
    float* out_probs = (float*)d_out + (size_t)B_ * S_ * E_;

    bf16 *qih, *qil, *kih, *kil, *vih, *vil;
    bf16 *wqh, *wql, *wkh, *wkl, *wvh, *wvl, *woh, *wol;
    bf16 *Qh, *Ql, *Kh, *Kl, *Vh, *Vl, *Ch, *Cl;
    SYM(qih, g_qin_hi); SYM(qil, g_qin_lo);
    SYM(kih, g_kin_hi); SYM(kil, g_kin_lo);
    SYM(vih, g_vin_hi); SYM(vil, g_vin_lo);
    SYM(wqh, g_Wq_hi); SYM(wql, g_Wq_lo);
    SYM(wkh, g_Wk_hi); SYM(wkl, g_Wk_lo);
    SYM(wvh, g_Wv_hi); SYM(wvl, g_Wv_lo);
    SYM(woh, g_Wo_hi); SYM(wol, g_Wo_lo);
    SYM(Qh, g_Q_hi); SYM(Ql, g_Q_lo);
    SYM(Kh, g_K_hi); SYM(Kl, g_K_lo);
    SYM(Vh, g_Vt_hi); SYM(Vl, g_Vt_lo);
    SYM(Ch, g_C_hi); SYM(Cl, g_C_lo);

    const int M = B_ * S_;  // 4096

    static int configured = 0;
    if (!configured) {
        cudaFuncSetAttribute(fused_attn_kernel,
                             cudaFuncAttributeMaxDynamicSharedMemorySize, 139264);
        configured = 1;
    }

    // preprocessing
    tw_kernel<<<(S_ * S_ / 4) / 256, 256>>>(ldist);
    split_kernel<<<2048, 256>>>(query, qih, qil, M * E_ / 4);
    split_kernel<<<2048, 256>>>(key,   kih, kil, M * E_ / 4);
    split_kernel<<<2048, 256>>>(value, vih, vil, M * E_ / 4);
    split_kernel<<<256, 256>>>(Wq, wqh, wql, E_ * E_ / 4);
    split_kernel<<<256, 256>>>(Wk, wkh, wkl, E_ * E_ / 4);
    split_kernel<<<256, 256>>>(Wv, wvh, wvl, E_ * E_ / 4);
    split_kernel<<<256, 256>>>(Wo, woh, wol, E_ * E_ / 4);

    // projections (write split head layouts)
    dim3 gp(E_ / 128, M / 128);
    k_mm<2, 4, 128, 128, 0><<<gp, 256>>>(qih, qil, wqh, wql, bq, nullptr, Qh, Ql, E_);
    k_mm<2, 4, 128, 128, 0><<<gp, 256>>>(kih, kil, wkh, wkl, bk, nullptr, Kh, Kl, E_);
    k_mm<2, 4, 128, 128, 3><<<gp, 256>>>(vih, vil, wvh, wvl, bv, nullptr, Vh, Vl, E_);

    // fused attention: scores + softmax + P.V
    dim3 ga(S_ / 128, B_ * H_);
    fused_attn_kernel<<<ga, 256, 139264>>>(tmask, tbias, out_probs);

    // output projection
    k_mm<2, 4, 128, 128, 1><<<gp, 256>>>(Ch, Cl, woh, wol, bo, out_attn, nullptr, nullptr, E_);
}

// round 5
// speedup vs baseline: 1.7584x; 1.7584x over previous
#include <cuda_runtime.h>
#include <cuda_bf16.h>
#include <math.h>
#include <stdint.h>

#define B_ 2
#define S_ 2048
#define E_ 512
#define H_ 8
#define DH_ 64
#define SCALE_ 0.125f  // 64^-0.5

#define BK 16          // fp32-equiv k per mainloop iter
#define SK 40          // smem row stride in bf16: 16 hi + 16 lo + 8 pad = 80B
#define SKS 20         // raw-s smem row stride in floats: 16 + 4 pad = 80B

typedef __nv_bfloat16 bf16;
typedef __nv_bfloat162 bf162;

// ---- scratch (device globals; allocation is forbidden) ----
__device__ bf16 g_qin_hi[4096 * 512], g_qin_lo[4096 * 512];
__device__ bf16 g_kin_hi[4096 * 512], g_kin_lo[4096 * 512];
__device__ bf16 g_vin_hi[4096 * 512], g_vin_lo[4096 * 512];
__device__ bf16 g_Wq_hi[512 * 512], g_Wq_lo[512 * 512];
__device__ bf16 g_Wk_hi[512 * 512], g_Wk_lo[512 * 512];
__device__ bf16 g_Wv_hi[512 * 512], g_Wv_lo[512 * 512];
__device__ bf16 g_Wo_hi[512 * 512], g_Wo_lo[512 * 512];
__device__ bf16 g_Q_hi[16 * 2048 * 64], g_Q_lo[16 * 2048 * 64];    // [bh][s][d]
__device__ bf16 g_K_hi[16 * 2048 * 64], g_K_lo[16 * 2048 * 64];    // [bh][s][d]
__device__ bf16 g_Vt_hi[16 * 64 * 2048], g_Vt_lo[16 * 64 * 2048];  // [bh][d][s]
__device__ bf16 g_C_hi[4096 * 512], g_C_lo[4096 * 512];            // ctx [m][e]
__device__ float g_tw[S_ * S_];
__device__ float g_pm[16 * 16 * 2048];   // per (bh, col-tile, row) partial max
__device__ float g_pl[16 * 16 * 2048];   // per (bh, col-tile, row) partial sumexp
__device__ float g_m[16 * 2048];         // per (bh, row) final max
__device__ float g_linv[16 * 2048];      // per (bh, row) 1/l

// ---------------------------------------------------------------------------
__global__ void tw_kernel(const float* __restrict__ ld) {
    int i = blockIdx.x * blockDim.x + threadIdx.x;
    float4 v = ((const float4*)ld)[i];
    float4 o = make_float4(__expf(-v.x), __expf(-v.y), __expf(-v.z), __expf(-v.w));
    ((float4*)g_tw)[i] = o;
}

__global__ void split_kernel(const float* __restrict__ src, bf16* __restrict__ hi,
                             bf16* __restrict__ lo, int n4) {
    int i = blockIdx.x * blockDim.x + threadIdx.x;
    if (i >= n4) return;
    float4 v = ((const float4*)src)[i];
    bf16 h0 = __float2bfloat16(v.x), h1 = __float2bfloat16(v.y);
    bf16 h2 = __float2bfloat16(v.z), h3 = __float2bfloat16(v.w);
    ((bf162*)hi)[2 * i]     = __halves2bfloat162(h0, h1);
    ((bf162*)hi)[2 * i + 1] = __halves2bfloat162(h2, h3);
    ((bf162*)lo)[2 * i] = __halves2bfloat162(
        __float2bfloat16(v.x - __bfloat162float(h0)),
        __float2bfloat16(v.y - __bfloat162float(h1)));
    ((bf162*)lo)[2 * i + 1] = __halves2bfloat162(
        __float2bfloat16(v.z - __bfloat162float(h2)),
        __float2bfloat16(v.w - __bfloat162float(h3)));
}

// ---------------------------------------------------------------------------
__device__ __forceinline__ void ldsm4(uint32_t addr, uint32_t& r0, uint32_t& r1,
                                      uint32_t& r2, uint32_t& r3) {
    asm volatile("ldmatrix.sync.aligned.m8n8.x4.shared.b16 {%0,%1,%2,%3}, [%4];"
                 : "=r"(r0), "=r"(r1), "=r"(r2), "=r"(r3) : "r"(addr));
}

__device__ __forceinline__ void mma16816(float* c, const uint32_t* a, const uint32_t* b) {
    asm volatile(
        "mma.sync.aligned.m16n8k16.row.col.f32.bf16.bf16.f32 "
        "{%0,%1,%2,%3}, {%4,%5,%6,%7}, {%8,%9}, {%0,%1,%2,%3};\n"
        : "+f"(c[0]), "+f"(c[1]), "+f"(c[2]), "+f"(c[3])
        : "r"(a[0]), "r"(a[1]), "r"(a[2]), "r"(a[3]), "r"(b[0]), "r"(b[1]));
}

__device__ __forceinline__ void cpa16(uint32_t dst, const void* src) {
    asm volatile("cp.async.cg.shared.global [%0], [%1], 16;" :: "r"(dst), "l"(src));
}
__device__ __forceinline__ void cp_commit() { asm volatile("cp.async.commit_group;"); }
template <int N>
__device__ __forceinline__ void cp_wait() { asm volatile("cp.async.wait_group %0;" :: "n"(N)); }

// [ROWS x 16] hi+lo tile loader, row layout [hi16|lo16|pad8], stride SK
template <int ROWS>
__device__ __forceinline__ void stage_load(const bf16* __restrict__ hi,
                                           const bf16* __restrict__ lo,
                                           int lda, int k0, uint32_t sdst, int tid) {
    #pragma unroll
    for (int i = 0; i < ROWS * 4 / 256; i++) {
        int idx = tid + i * 256;
        int r = idx >> 2, c = idx & 3;
        const bf16* src = ((c < 2) ? hi : lo) + (size_t)r * lda + k0 + (c & 1) * 8;
        uint32_t dst = sdst + (r * SK + ((c < 2) ? 0 : 16) + (c & 1) * 8) * 2;
        cpa16(dst, src);
    }
}

// ---------------------------------------------------------------------------
// D[M,N] = A . B^T in 3xBF16, double-buffered cp.async pipeline.
// MODE 0: split head layout [bh][s][d] (+bias)   MODE 3: split transposed [bh][d][s]
// MODE 1: fp32 [M,512] (+bias)
// MODE 2: scores: *SCALE + tbias*tw, mask -> raw s to P; also per-tile row stats
// ---------------------------------------------------------------------------
template <int WARPS_M, int WARPS_N, int BM, int BN, int MODE>
__global__ __launch_bounds__(256) void k_mm(
    const bf16* __restrict__ Ahi, const bf16* __restrict__ Alo,
    const bf16* __restrict__ Bhi, const bf16* __restrict__ Blo,
    const float* __restrict__ bias, float* __restrict__ out,
    bf16* __restrict__ outHi, bf16* __restrict__ outLo,
    int K, long long sAz, long long sBz,
    const int* __restrict__ mask, const float* __restrict__ tbias) {
    constexpr int WM = BM / WARPS_M;
    constexpr int WN = BN / WARPS_N;
    constexpr int MF = WM / 16;
    constexpr int NF = WN / 8;
    constexpr int STAGE = (BM + BN) * SK;

    __shared__ bf16 smem[2 * STAGE];
    __shared__ float red_s[WARPS_N][BM];
    __shared__ float rowm_s[BM];

    const int tid = threadIdx.x, wid = tid >> 5, lane = tid & 31;
    const int wm = wid % WARPS_M, wn = wid / WARPS_M;
    const int bz = blockIdx.z;
    const int m0 = blockIdx.y * BM, n0 = blockIdx.x * BN;

    const bf16* Ahp = Ahi + (long long)bz * sAz + (size_t)m0 * K;
    const bf16* Alp = Alo + (long long)bz * sAz + (size_t)m0 * K;
    const bf16* Bhp = Bhi + (long long)bz * sBz + (size_t)n0 * K;
    const bf16* Blp = Blo + (long long)bz * sBz + (size_t)n0 * K;

    float acc[MF][NF][4];
    #pragma unroll
    for (int i = 0; i < MF; i++)
        #pragma unroll
        for (int j = 0; j < NF; j++)
            #pragma unroll
            for (int q = 0; q < 4; q++) acc[i][j][q] = 0.f;

    const uint32_t sbase = (uint32_t)__cvta_generic_to_shared(smem);
    const int t8 = lane >> 3, r8 = lane & 7;
    const int frow = r8 + 8 * (t8 & 1);
    const int fcol = 8 * (t8 >> 1);

    const int niter = K / BK;
    stage_load<BM>(Ahp, Alp, K, 0, sbase, tid);
    stage_load<BN>(Bhp, Blp, K, 0, sbase + BM * SK * 2, tid);
    cp_commit();

    for (int it = 0; it < niter; it++) {
        if (it + 1 < niter) {
            uint32_t sd = sbase + ((it + 1) & 1) * STAGE * 2;
            stage_load<BM>(Ahp, Alp, K, (it + 1) * BK, sd, tid);
            stage_load<BN>(Bhp, Blp, K, (it + 1) * BK, sd + BM * SK * 2, tid);
            cp_commit();
            cp_wait<1>();
        } else {
            cp_wait<0>();
        }
        __syncthreads();

        const uint32_t sA = sbase + (it & 1) * STAGE * 2;
        const uint32_t sB = sA + BM * SK * 2;
        #pragma unroll
        for (int p = 0; p < 3; p++) {
            const int ao = (p == 2) ? 16 : 0;
            const int bo = (p == 1) ? 16 : 0;
            uint32_t af[MF][4], bf[NF][2];
            #pragma unroll
            for (int mf = 0; mf < MF; mf++) {
                uint32_t addr = sA + ((wm * WM + mf * 16 + frow) * SK + ao + fcol) * 2;
                ldsm4(addr, af[mf][0], af[mf][1], af[mf][2], af[mf][3]);
            }
            #pragma unroll
            for (int nf2 = 0; nf2 < NF / 2; nf2++) {
                uint32_t r0, r1, r2, r3;
                uint32_t addr = sB + ((wn * WN + nf2 * 16 + frow) * SK + bo + fcol) * 2;
                ldsm4(addr, r0, r1, r2, r3);
                bf[2 * nf2][0] = r0;      bf[2 * nf2][1] = r2;
                bf[2 * nf2 + 1][0] = r1;  bf[2 * nf2 + 1][1] = r3;
            }
            #pragma unroll
            for (int mf = 0; mf < MF; mf++)
                #pragma unroll
                for (int nf = 0; nf < NF; nf++)
                    mma16816(acc[mf][nf], af[mf], bf[nf]);
        }
        __syncthreads();
    }

    const int lrow = lane >> 2, lcol = (lane & 3) * 2;
    #pragma unroll
    for (int mf = 0; mf < MF; mf++) {
        #pragma unroll
        for (int nf = 0; nf < NF; nf++) {
            #pragma unroll
            for (int hh = 0; hh < 2; hh++) {
                int m = m0 + wm * WM + mf * 16 + lrow + hh * 8;
                int n = n0 + wn * WN + nf * 8 + lcol;
                float v0 = acc[mf][nf][2 * hh];
                float v1 = acc[mf][nf][2 * hh + 1];
                if (MODE == 0) {
                    int b = m >> 11, s = m & 2047;
                    int h = n >> 6, d = n & 63;
                    size_t o = (((size_t)(b * H_ + h) * S_ + s) << 6) + d;
                    float x0 = v0 + bias[n], x1 = v1 + bias[n + 1];
                    bf16 h0 = __float2bfloat16(x0), h1 = __float2bfloat16(x1);
                    *(bf162*)&outHi[o] = __halves2bfloat162(h0, h1);
                    *(bf162*)&outLo[o] = __halves2bfloat162(
                        __float2bfloat16(x0 - __bfloat162float(h0)),
                        __float2bfloat16(x1 - __bfloat162float(h1)));
                } else if (MODE == 3) {
                    int b = m >> 11, s = m & 2047;
                    int h = n >> 6, d = n & 63;
                    size_t base = (size_t)(b * H_ + h) * DH_;
                    float x0 = v0 + bias[n], x1 = v1 + bias[n + 1];
                    bf16 h0 = __float2bfloat16(x0), h1 = __float2bfloat16(x1);
                    outHi[(base + d) * S_ + s] = h0;
                    outHi[(base + d + 1) * S_ + s] = h1;
                    outLo[(base + d) * S_ + s] = __float2bfloat16(x0 - __bfloat162float(h0));
                    outLo[(base + d + 1) * S_ + s] = __float2bfloat16(x1 - __bfloat162float(h1));
                } else if (MODE == 1) {
                    float2 val = make_float2(v0 + bias[n], v1 + bias[n + 1]);
                    *(float2*)&out[(size_t)m * 512 + n] = val;
                } else {  // MODE 2: scores (raw s) — keep values in acc for stats
                    int h = bz & 7;
                    float tb = tbias[h];
                    size_t mn = (size_t)m * S_ + n;
                    float2 tw = *(const float2*)&g_tw[mn];
                    int2 mk = *(const int2*)&mask[mn];
                    float s0 = v0 * SCALE_ + tb * tw.x;
                    float s1 = v1 * SCALE_ + tb * tw.y;
                    if (mk.x == 0) s0 = -1e9f;
                    if (mk.y == 0) s1 = -1e9f;
                    *(float2*)&out[(size_t)bz * S_ * S_ + mn] = make_float2(s0, s1);
                    acc[mf][nf][2 * hh] = s0;
                    acc[mf][nf][2 * hh + 1] = s1;
                }
            }
        }
    }

    if (MODE == 2) {
        // per-warp row max over its WN cols
        #pragma unroll
        for (int mf = 0; mf < MF; mf++) {
            #pragma unroll
            for (int hh = 0; hh < 2; hh++) {
                float mx = -INFINITY;
                #pragma unroll
                for (int nf = 0; nf < NF; nf++)
                    mx = fmaxf(mx, fmaxf(acc[mf][nf][2 * hh], acc[mf][nf][2 * hh + 1]));
                mx = fmaxf(mx, __shfl_xor_sync(0xffffffffu, mx, 1));
                mx = fmaxf(mx, __shfl_xor_sync(0xffffffffu, mx, 2));
                if ((lane & 3) == 0)
                    red_s[wn][wm * WM + mf * 16 + lrow + hh * 8] = mx;
            }
        }
        __syncthreads();
        if (tid < BM) {
            float mx = red_s[0][tid];
            #pragma unroll
            for (int w = 1; w < WARPS_N; w++) mx = fmaxf(mx, red_s[w][tid]);
            rowm_s[tid] = mx;
        }
        __syncthreads();
        // per-warp row sumexp
        #pragma unroll
        for (int mf = 0; mf < MF; mf++) {
            #pragma unroll
            for (int hh = 0; hh < 2; hh++) {
                int row = wm * WM + mf * 16 + lrow + hh * 8;
                float rm = rowm_s[row];
                float sm = 0.f;
                #pragma unroll
                for (int nf = 0; nf < NF; nf++)
                    sm += __expf(acc[mf][nf][2 * hh] - rm) +
                          __expf(acc[mf][nf][2 * hh + 1] - rm);
                sm += __shfl_xor_sync(0xffffffffu, sm, 1);
                sm += __shfl_xor_sync(0xffffffffu, sm, 2);
                if ((lane & 3) == 0) red_s[wn][row] = sm;
            }
        }
        __syncthreads();
        if (tid < BM) {
            float l = red_s[0][tid];
            #pragma unroll
            for (int w = 1; w < WARPS_N; w++) l += red_s[w][tid];
            size_t o = ((size_t)bz * 16 + blockIdx.x) * S_ + m0 + tid;
            g_pm[o] = rowm_s[tid];
            g_pl[o] = l;
        }
    }
}

// ---------------------------------------------------------------------------
// combine per-tile stats -> per-row (m, 1/l)
// ---------------------------------------------------------------------------
__global__ void combine_kernel() {
    int idx = blockIdx.x * 256 + threadIdx.x;   // bz*2048 + r, 32768 total
    int bz = idx >> 11, r = idx & 2047;
    float mt[16];
    float mx = -INFINITY;
    #pragma unroll
    for (int t = 0; t < 16; t++) {
        mt[t] = g_pm[((size_t)bz * 16 + t) * S_ + r];
        mx = fmaxf(mx, mt[t]);
    }
    float l = 0.f;
    #pragma unroll
    for (int t = 0; t < 16; t++)
        l += g_pl[((size_t)bz * 16 + t) * S_ + r] * __expf(mt[t] - mx);
    g_m[idx] = mx;
    g_linv[idx] = 1.0f / l;
}

// ---------------------------------------------------------------------------
// ctx kernel: read raw s, finalize softmax, write fp32 P, P.V via 3xBF16 MMA.
// grid (1, S/128, B*H), 256 threads, 8 warps (WARPS_M=4, WARPS_N=2).
// ---------------------------------------------------------------------------
__global__ __launch_bounds__(256) void ctx_kernel(float* __restrict__ P) {
    __shared__ float sS[2][128 * SKS];
    __shared__ bf16 sP[128 * SK];
    __shared__ bf16 sV[2][64 * SK];
    __shared__ float sm_m[128], sm_li[128];

    const int tid = threadIdx.x, wid = tid >> 5, lane = tid & 31;
    const int wm = wid % 4, wn = wid / 4;
    const int bz = blockIdx.z;
    const int b = bz >> 3, h = bz & 7;
    const int m0 = blockIdx.y * 128;

    float* Pbh = P + (size_t)bz * S_ * S_;
    const bf16* Vh0 = g_Vt_hi + (size_t)bz * DH_ * S_;
    const bf16* Vl0 = g_Vt_lo + (size_t)bz * DH_ * S_;

    if (tid < 128) {
        sm_m[tid]  = g_m[bz * S_ + m0 + tid];
        sm_li[tid] = g_linv[bz * S_ + m0 + tid];
    }

    float acc[2][4][4];
    #pragma unroll
    for (int i = 0; i < 2; i++)
        #pragma unroll
        for (int j = 0; j < 4; j++)
            #pragma unroll
            for (int q = 0; q < 4; q++) acc[i][j][q] = 0.f;

    const uint32_t uS0 = (uint32_t)__cvta_generic_to_shared(sS);
    const uint32_t uP = (uint32_t)__cvta_generic_to_shared(sP);
    const uint32_t uV0 = (uint32_t)__cvta_generic_to_shared(sV);
    const int t8 = lane >> 3, r8 = lane & 7;
    const int frow = r8 + 8 * (t8 & 1), fcol = 8 * (t8 >> 1);
    const int lrow = lane >> 2, lcol = (lane & 3) * 2;

    // prologue: stage 0 (raw s chunk + V chunk)
    {
        #pragma unroll
        for (int i = 0; i < 2; i++) {
            int idx = tid + i * 256;
            int r = idx >> 2, c = (idx & 3) * 4;
            cpa16(uS0 + (r * SKS + c) * 4, Pbh + (size_t)(m0 + r) * S_ + c);
        }
        stage_load<64>(Vh0, Vl0, S_, 0, uV0, tid);
        cp_commit();
    }

    const int cr = tid >> 1, cc = (tid & 1) * 8;   // convert assignment
    for (int it = 0; it < 128; it++) {
        if (it + 1 < 128) {
            uint32_t sd = uS0 + ((it + 1) & 1) * (128 * SKS * 4);
            #pragma unroll
            for (int i = 0; i < 2; i++) {
                int idx = tid + i * 256;
                int r = idx >> 2, c = (idx & 3) * 4;
                cpa16(sd + (r * SKS + c) * 4,
                      Pbh + (size_t)(m0 + r) * S_ + (it + 1) * 16 + c);
            }
            stage_load<64>(Vh0, Vl0, S_, (it + 1) * 16,
                           uV0 + ((it + 1) & 1) * (64 * SK * 2), tid);
            cp_commit();
            cp_wait<1>();
        } else {
            cp_wait<0>();
        }
        __syncthreads();

        // finalize p = exp(s - m) * linv ; write fp32 P ; split into sP
        {
            const float* ss = sS[it & 1] + cr * SKS + cc;
            float mrow = sm_m[cr], li = sm_li[cr];
            float4 a = *(const float4*)(ss);
            float4 c4 = *(const float4*)(ss + 4);
            float p0 = __expf(a.x - mrow) * li, p1 = __expf(a.y - mrow) * li;
            float p2 = __expf(a.z - mrow) * li, p3 = __expf(a.w - mrow) * li;
            float p4 = __expf(c4.x - mrow) * li, p5 = __expf(c4.y - mrow) * li;
            float p6 = __expf(c4.z - mrow) * li, p7 = __expf(c4.w - mrow) * li;
            float* gdst = Pbh + (size_t)(m0 + cr) * S_ + it * 16 + cc;
            *(float4*)gdst = make_float4(p0, p1, p2, p3);
            *(float4*)(gdst + 4) = make_float4(p4, p5, p6, p7);
            bf16 h0 = __float2bfloat16(p0), h1 = __float2bfloat16(p1);
            bf16 h2 = __float2bfloat16(p2), h3 = __float2bfloat16(p3);
            bf16 h4 = __float2bfloat16(p4), h5 = __float2bfloat16(p5);
            bf16 h6 = __float2bfloat16(p6), h7 = __float2bfloat16(p7);
            uint4 hv, lv;
            ((bf162*)&hv)[0] = __halves2bfloat162(h0, h1);
            ((bf162*)&hv)[1] = __halves2bfloat162(h2, h3);
            ((bf162*)&hv)[2] = __halves2bfloat162(h4, h5);
            ((bf162*)&hv)[3] = __halves2bfloat162(h6, h7);
            ((bf162*)&lv)[0] = __halves2bfloat162(
                __float2bfloat16(p0 - __bfloat162float(h0)),
                __float2bfloat16(p1 - __bfloat162float(h1)));
            ((bf162*)&lv)[1] = __halves2bfloat162(
                __float2bfloat16(p2 - __bfloat162float(h2)),
                __float2bfloat16(p3 - __bfloat162float(h3)));
            ((bf162*)&lv)[2] = __halves2bfloat162(
                __float2bfloat16(p4 - __bfloat162float(h4)),
                __float2bfloat16(p5 - __bfloat162float(h5)));
            ((bf162*)&lv)[3] = __halves2bfloat162(
                __float2bfloat16(p6 - __bfloat162float(h6)),
                __float2bfloat16(p7 - __bfloat162float(h7)));
            *(uint4*)&sP[cr * SK + cc] = hv;
            *(uint4*)&sP[cr * SK + 16 + cc] = lv;
        }
        __syncthreads();

        const uint32_t sVt = uV0 + (it & 1) * (64 * SK * 2);
        #pragma unroll
        for (int p = 0; p < 3; p++) {
            const int ao = (p == 2) ? 16 : 0;
            const int bo = (p == 1) ? 16 : 0;
            uint32_t af[2][4], bf[4][2];
            #pragma unroll
            for (int mf = 0; mf < 2; mf++) {
                uint32_t addr = uP + ((wm * 32 + mf * 16 + frow) * SK + ao + fcol) * 2;
                ldsm4(addr, af[mf][0], af[mf][1], af[mf][2], af[mf][3]);
            }
            #pragma unroll
            for (int nf2 = 0; nf2 < 2; nf2++) {
                uint32_t r0, r1, r2, r3;
                uint32_t addr = sVt + ((wn * 32 + nf2 * 16 + frow) * SK + bo + fcol) * 2;
                ldsm4(addr, r0, r1, r2, r3);
                bf[2 * nf2][0] = r0;      bf[2 * nf2][1] = r2;
                bf[2 * nf2 + 1][0] = r1;  bf[2 * nf2 + 1][1] = r3;
            }
            #pragma unroll
            for (int mf = 0; mf < 2; mf++)
                #pragma unroll
                for (int nf = 0; nf < 4; nf++)
                    mma16816(acc[mf][nf], af[mf], bf[nf]);
        }
        __syncthreads();
    }

    // epilogue: write split ctx [b][m][h*64+d]
    #pragma unroll
    for (int mf = 0; mf < 2; mf++) {
        #pragma unroll
        for (int nf = 0; nf < 4; nf++) {
            #pragma unroll
            for (int hh = 0; hh < 2; hh++) {
                int m = m0 + wm * 32 + mf * 16 + lrow + hh * 8;
                int d = wn * 32 + nf * 8 + lcol;
                size_t o = ((size_t)b * S_ + m) * E_ + h * DH_ + d;
                float v0 = acc[mf][nf][2 * hh], v1 = acc[mf][nf][2 * hh + 1];
                bf16 h0 = __float2bfloat16(v0), h1 = __float2bfloat16(v1);
                *(bf162*)&g_C_hi[o] = __halves2bfloat162(h0, h1);
                *(bf162*)&g_C_lo[o] = __halves2bfloat162(
                    __float2bfloat16(v0 - __bfloat162float(h0)),
                    __float2bfloat16(v1 - __bfloat162float(h1)));
            }
        }
    }
}

// ---------------------------------------------------------------------------
#define SYM(p, s) cudaGetSymbolAddress((void**)&p, s)

extern "C" void kernel_launch(void* const* d_in, const int* in_sizes, int n_in,
                              void* d_out, int out_size) {
    const float* query = (const float*)d_in[0];
    const float* key   = (const float*)d_in[1];
    const float* value = (const float*)d_in[2];
    const int*   tmask = (const int*)d_in[3];
    const float* ldist = (const float*)d_in[4];
    const float* Wq = (const float*)d_in[5];
    const float* bq = (const float*)d_in[6];
    const float* Wk = (const float*)d_in[7];
    const float* bk = (const float*)d_in[8];
    const float* Wv = (const float*)d_in[9];
    const float* bv = (const float*)d_in[10];
    const float* Wo = (const float*)d_in[11];
    const float* bo = (const float*)d_in[12];
    const float* tbias = (const float*)d_in[13];

    float* out_attn  = (float*)d_out;
    float* out_probs = (float*)d_out + (size_t)B_ * S_ * E_;

    bf16 *qih, *qil, *kih, *kil, *vih, *vil;
    bf16 *wqh, *wql, *wkh, *wkl, *wvh, *wvl, *woh, *wol;
    bf16 *Qh, *Ql, *Kh, *Kl, *Vh, *Vl, *Ch, *Cl;
    SYM(qih, g_qin_hi); SYM(qil, g_qin_lo);
    SYM(kih, g_kin_hi); SYM(kil, g_kin_lo);
    SYM(vih, g_vin_hi); SYM(vil, g_vin_lo);
    SYM(wqh, g_Wq_hi); SYM(wql, g_Wq_lo);
    SYM(wkh, g_Wk_hi); SYM(wkl, g_Wk_lo);
    SYM(wvh, g_Wv_hi); SYM(wvl, g_Wv_lo);
    SYM(woh, g_Wo_hi); SYM(wol, g_Wo_lo);
    SYM(Qh, g_Q_hi); SYM(Ql, g_Q_lo);
    SYM(Kh, g_K_hi); SYM(Kl, g_K_lo);
    SYM(Vh, g_Vt_hi); SYM(Vl, g_Vt_lo);
    SYM(Ch, g_C_hi); SYM(Cl, g_C_lo);

    const int M = B_ * S_;  // 4096

    // preprocessing
    tw_kernel<<<(S_ * S_ / 4) / 256, 256>>>(ldist);
    split_kernel<<<2048, 256>>>(query, qih, qil, M * E_ / 4);
    split_kernel<<<2048, 256>>>(key,   kih, kil, M * E_ / 4);
    split_kernel<<<2048, 256>>>(value, vih, vil, M * E_ / 4);
    split_kernel<<<256, 256>>>(Wq, wqh, wql, E_ * E_ / 4);
    split_kernel<<<256, 256>>>(Wk, wkh, wkl, E_ * E_ / 4);
    split_kernel<<<256, 256>>>(Wv, wvh, wvl, E_ * E_ / 4);
    split_kernel<<<256, 256>>>(Wo, woh, wol, E_ * E_ / 4);

    // projections (write split head layouts)
    dim3 gp(E_ / 128, M / 128);
    k_mm<2, 4, 128, 128, 0><<<gp, 256>>>(qih, qil, wqh, wql, bq, nullptr, Qh, Ql,
                                         E_, 0, 0, nullptr, nullptr);
    k_mm<2, 4, 128, 128, 0><<<gp, 256>>>(kih, kil, wkh, wkl, bk, nullptr, Kh, Kl,
                                         E_, 0, 0, nullptr, nullptr);
    k_mm<2, 4, 128, 128, 3><<<gp, 256>>>(vih, vil, wvh, wvl, bv, nullptr, Vh, Vl,
                                         E_, 0, 0, nullptr, nullptr);

    // scores (raw s + per-tile stats)
    dim3 gs(S_ / 128, S_ / 128, B_ * H_);
    k_mm<2, 4, 128, 128, 2><<<gs, 256>>>(Qh, Ql, Kh, Kl, nullptr, out_probs,
                                         nullptr, nullptr, DH_,
                                         (long long)S_ * DH_, (long long)S_ * DH_,
                                         tmask, tbias);

    // combine stats
    combine_kernel<<<128, 256>>>();

    // ctx: finalize softmax + P.V
    dim3 gc(1, S_ / 128, B_ * H_);
    ctx_kernel<<<gc, 256>>>(out_probs);

    // output projection
    k_mm<2, 4, 128, 128, 1><<<gp, 256>>>(Ch, Cl, woh, wol, bo, out_attn,
                                         nullptr, nullptr, E_, 0, 0, nullptr, nullptr);
}

// round 7
// speedup vs baseline: 1.8382x; 1.0454x over previous
#include <cuda_runtime.h>
#include <cuda_bf16.h>
#include <math.h>
#include <stdint.h>

#define B_ 2
#define S_ 2048
#define E_ 512
#define H_ 8
#define DH_ 64
#define SCALE_ 0.125f  // 64^-0.5

#define BK 16          // fp32-equiv k per mainloop iter (k_mm)
#define SK 40          // k_mm smem row stride: 16 hi + 16 lo + 8 pad = 80B

typedef __nv_bfloat16 bf16;
typedef __nv_bfloat162 bf162;

// ---- scratch (device globals; allocation is forbidden) ----
__device__ bf16 g_qin_hi[4096 * 512], g_qin_lo[4096 * 512];
__device__ bf16 g_kin_hi[4096 * 512], g_kin_lo[4096 * 512];
__device__ bf16 g_vin_hi[4096 * 512], g_vin_lo[4096 * 512];
__device__ bf16 g_Wq_hi[512 * 512], g_Wq_lo[512 * 512];
__device__ bf16 g_Wk_hi[512 * 512], g_Wk_lo[512 * 512];
__device__ bf16 g_Wv_hi[512 * 512], g_Wv_lo[512 * 512];
__device__ bf16 g_Wo_hi[512 * 512], g_Wo_lo[512 * 512];
__device__ bf16 g_Q_hi[16 * 2048 * 64], g_Q_lo[16 * 2048 * 64];    // [bh][s][d]
__device__ bf16 g_K_hi[16 * 2048 * 64], g_K_lo[16 * 2048 * 64];    // [bh][s][d]
__device__ bf16 g_Vt_hi[16 * 64 * 2048], g_Vt_lo[16 * 64 * 2048];  // [bh][d][s]
__device__ bf16 g_C_hi[4096 * 512], g_C_lo[4096 * 512];            // ctx [m][e]
__device__ float g_tw[S_ * S_];
__device__ float g_pm[16 * 16 * 2048];
__device__ float g_pl[16 * 16 * 2048];
__device__ float g_m[16 * 2048];
__device__ float g_linv[16 * 2048];

// ---------------------------------------------------------------------------
__global__ void tw_kernel(const float* __restrict__ ld) {
    int i = blockIdx.x * blockDim.x + threadIdx.x;
    float4 v = ((const float4*)ld)[i];
    ((float4*)g_tw)[i] =
        make_float4(__expf(-v.x), __expf(-v.y), __expf(-v.z), __expf(-v.w));
}

__device__ __forceinline__ void split4f(const float* __restrict__ src,
                                        bf16* __restrict__ hi,
                                        bf16* __restrict__ lo, int i) {
    float4 v = ((const float4*)src)[i];
    bf16 h0 = __float2bfloat16(v.x), h1 = __float2bfloat16(v.y);
    bf16 h2 = __float2bfloat16(v.z), h3 = __float2bfloat16(v.w);
    ((bf162*)hi)[2 * i]     = __halves2bfloat162(h0, h1);
    ((bf162*)hi)[2 * i + 1] = __halves2bfloat162(h2, h3);
    ((bf162*)lo)[2 * i] = __halves2bfloat162(
        __float2bfloat16(v.x - __bfloat162float(h0)),
        __float2bfloat16(v.y - __bfloat162float(h1)));
    ((bf162*)lo)[2 * i + 1] = __halves2bfloat162(
        __float2bfloat16(v.z - __bfloat162float(h2)),
        __float2bfloat16(v.w - __bfloat162float(h3)));
}

// 3 big input splits in one launch (z selects tensor)
__global__ void split_in_kernel(const float* __restrict__ q,
                                const float* __restrict__ k,
                                const float* __restrict__ v) {
    int z = blockIdx.z;
    const float* src = (z == 0) ? q : (z == 1) ? k : v;
    bf16* hi = (z == 0) ? g_qin_hi : (z == 1) ? g_kin_hi : g_vin_hi;
    bf16* lo = (z == 0) ? g_qin_lo : (z == 1) ? g_kin_lo : g_vin_lo;
    split4f(src, hi, lo, blockIdx.x * 256 + threadIdx.x);
}

// 4 weight splits in one launch
__global__ void split_w_kernel(const float* __restrict__ wq,
                               const float* __restrict__ wk,
                               const float* __restrict__ wv,
                               const float* __restrict__ wo) {
    int z = blockIdx.z;
    const float* src = (z == 0) ? wq : (z == 1) ? wk : (z == 2) ? wv : wo;
    bf16* hi = (z == 0) ? g_Wq_hi : (z == 1) ? g_Wk_hi : (z == 2) ? g_Wv_hi : g_Wo_hi;
    bf16* lo = (z == 0) ? g_Wq_lo : (z == 1) ? g_Wk_lo : (z == 2) ? g_Wv_lo : g_Wo_lo;
    split4f(src, hi, lo, blockIdx.x * 256 + threadIdx.x);
}

// ---------------------------------------------------------------------------
__device__ __forceinline__ void ldsm4(uint32_t addr, uint32_t& r0, uint32_t& r1,
                                      uint32_t& r2, uint32_t& r3) {
    asm volatile("ldmatrix.sync.aligned.m8n8.x4.shared.b16 {%0,%1,%2,%3}, [%4];"
                 : "=r"(r0), "=r"(r1), "=r"(r2), "=r"(r3) : "r"(addr));
}

__device__ __forceinline__ void mma16816(float* c, const uint32_t* a, const uint32_t* b) {
    asm volatile(
        "mma.sync.aligned.m16n8k16.row.col.f32.bf16.bf16.f32 "
        "{%0,%1,%2,%3}, {%4,%5,%6,%7}, {%8,%9}, {%0,%1,%2,%3};\n"
        : "+f"(c[0]), "+f"(c[1]), "+f"(c[2]), "+f"(c[3])
        : "r"(a[0]), "r"(a[1]), "r"(a[2]), "r"(a[3]), "r"(b[0]), "r"(b[1]));
}

__device__ __forceinline__ void cpa16(uint32_t dst, const void* src) {
    asm volatile("cp.async.cg.shared.global [%0], [%1], 16;" :: "r"(dst), "l"(src));
}
__device__ __forceinline__ void cp_commit() { asm volatile("cp.async.commit_group;"); }
template <int N>
__device__ __forceinline__ void cp_wait() { asm volatile("cp.async.wait_group %0;" :: "n"(N)); }

// [ROWS x 16] hi+lo tile loader, row layout [hi16|lo16|pad8], stride SK
template <int ROWS>
__device__ __forceinline__ void stage_load(const bf16* __restrict__ hi,
                                           const bf16* __restrict__ lo,
                                           int lda, int k0, uint32_t sdst, int tid) {
    #pragma unroll
    for (int i = 0; i < ROWS * 4 / 256; i++) {
        int idx = tid + i * 256;
        int r = idx >> 2, c = idx & 3;
        const bf16* src = ((c < 2) ? hi : lo) + (size_t)r * lda + k0 + (c & 1) * 8;
        uint32_t dst = sdst + (r * SK + ((c < 2) ? 0 : 16) + (c & 1) * 8) * 2;
        cpa16(dst, src);
    }
}

// ---------------------------------------------------------------------------
// 128x128 GEMM, 3xBF16, 4-stage cp.async pipeline, 1 sync/iter.
// MODE 5: fused QKV projections (z = 0/1/2 -> Q/K/V)
// MODE 2: scores (raw s + per-tile row stats)
// MODE 1: output projection -> fp32 out
// ---------------------------------------------------------------------------
template <int MODE>
__global__ __launch_bounds__(256) void k_mm(
    const float* __restrict__ b0, const float* __restrict__ b1,
    const float* __restrict__ b2, float* __restrict__ out,
    const int* __restrict__ mask, const float* __restrict__ tbias) {
    constexpr int NST = 4;
    constexpr int STB = 256 * SK * 2;        // bytes per stage (A 128 rows + B 128 rows)
    constexpr int K = (MODE == 2) ? 64 : 512;
    constexpr int niter = K / BK;

    extern __shared__ char smraw[];
    float* red_s  = (float*)(smraw + NST * STB);        // [4][128]
    float* rowm_s = red_s + 4 * 128;

    const int tid = threadIdx.x, wid = tid >> 5, lane = tid & 31;
    const int wm = wid & 1, wn = wid >> 1;   // WARPS_M=2, WARPS_N=4; WM=64, WN=32
    const int bz = blockIdx.z;
    const int m0 = blockIdx.y * 128, n0 = blockIdx.x * 128;

    const bf16 *Ahi, *Alo, *Bhi, *Blo;
    const float* bias = b0;
    if (MODE == 5) {
        if (bz == 0)      { Ahi = g_qin_hi; Alo = g_qin_lo; Bhi = g_Wq_hi; Blo = g_Wq_lo; bias = b0; }
        else if (bz == 1) { Ahi = g_kin_hi; Alo = g_kin_lo; Bhi = g_Wk_hi; Blo = g_Wk_lo; bias = b1; }
        else              { Ahi = g_vin_hi; Alo = g_vin_lo; Bhi = g_Wv_hi; Blo = g_Wv_lo; bias = b2; }
    } else if (MODE == 1) {
        Ahi = g_C_hi; Alo = g_C_lo; Bhi = g_Wo_hi; Blo = g_Wo_lo;
    } else {  // MODE 2
        size_t o = (size_t)bz * S_ * DH_;
        Ahi = g_Q_hi + o; Alo = g_Q_lo + o; Bhi = g_K_hi + o; Blo = g_K_lo + o;
    }
    const bf16* Ahp = Ahi + (size_t)m0 * K;
    const bf16* Alp = Alo + (size_t)m0 * K;
    const bf16* Bhp = Bhi + (size_t)n0 * K;
    const bf16* Blp = Blo + (size_t)n0 * K;

    float acc[4][4][4];
    #pragma unroll
    for (int i = 0; i < 4; i++)
        #pragma unroll
        for (int j = 0; j < 4; j++)
            #pragma unroll
            for (int q = 0; q < 4; q++) acc[i][j][q] = 0.f;

    const uint32_t sbase = (uint32_t)__cvta_generic_to_shared(smraw);
    const int t8 = lane >> 3, r8 = lane & 7;
    const int frow = r8 + 8 * (t8 & 1);
    const int fcol = 8 * (t8 >> 1);

    // prologue: stages 0..NST-2
    #pragma unroll
    for (int s = 0; s < NST - 1; s++) {
        stage_load<128>(Ahp, Alp, K, s * BK, sbase + s * STB, tid);
        stage_load<128>(Bhp, Blp, K, s * BK, sbase + s * STB + 128 * SK * 2, tid);
        cp_commit();
    }

    for (int it = 0; it < niter; it++) {
        cp_wait<NST - 2>();
        __syncthreads();
        // prefetch into the slot freed at iter it-1 (all warps past barrier)
        int pf = it + NST - 1;
        if (pf < niter) {
            uint32_t sd = sbase + (pf % NST) * STB;
            stage_load<128>(Ahp, Alp, K, pf * BK, sd, tid);
            stage_load<128>(Bhp, Blp, K, pf * BK, sd + 128 * SK * 2, tid);
        }
        cp_commit();

        const uint32_t sA = sbase + (it % NST) * STB;
        const uint32_t sB = sA + 128 * SK * 2;
        #pragma unroll
        for (int p = 0; p < 3; p++) {
            const int ao = (p == 2) ? 16 : 0;
            const int bo = (p == 1) ? 16 : 0;
            uint32_t af[4][4], bfr[4][2];
            #pragma unroll
            for (int mf = 0; mf < 4; mf++) {
                uint32_t addr = sA + ((wm * 64 + mf * 16 + frow) * SK + ao + fcol) * 2;
                ldsm4(addr, af[mf][0], af[mf][1], af[mf][2], af[mf][3]);
            }
            #pragma unroll
            for (int nf2 = 0; nf2 < 2; nf2++) {
                uint32_t r0, r1, r2, r3;
                uint32_t addr = sB + ((wn * 32 + nf2 * 16 + frow) * SK + bo + fcol) * 2;
                ldsm4(addr, r0, r1, r2, r3);
                bfr[2 * nf2][0] = r0;      bfr[2 * nf2][1] = r2;
                bfr[2 * nf2 + 1][0] = r1;  bfr[2 * nf2 + 1][1] = r3;
            }
            #pragma unroll
            for (int mf = 0; mf < 4; mf++)
                #pragma unroll
                for (int nf = 0; nf < 4; nf++)
                    mma16816(acc[mf][nf], af[mf], bfr[nf]);
        }
    }

    const int lrow = lane >> 2, lcol = (lane & 3) * 2;
    #pragma unroll
    for (int mf = 0; mf < 4; mf++) {
        #pragma unroll
        for (int nf = 0; nf < 4; nf++) {
            #pragma unroll
            for (int hh = 0; hh < 2; hh++) {
                int m = m0 + wm * 64 + mf * 16 + lrow + hh * 8;
                int n = n0 + wn * 32 + nf * 8 + lcol;
                float v0 = acc[mf][nf][2 * hh];
                float v1 = acc[mf][nf][2 * hh + 1];
                if (MODE == 5) {
                    int b = m >> 11, s = m & 2047;
                    int h = n >> 6, d = n & 63;
                    float x0 = v0 + bias[n], x1 = v1 + bias[n + 1];
                    bf16 h0 = __float2bfloat16(x0), h1 = __float2bfloat16(x1);
                    bf16 l0 = __float2bfloat16(x0 - __bfloat162float(h0));
                    bf16 l1 = __float2bfloat16(x1 - __bfloat162float(h1));
                    if (bz < 2) {
                        bf16* oh = (bz == 0) ? g_Q_hi : g_K_hi;
                        bf16* ol = (bz == 0) ? g_Q_lo : g_K_lo;
                        size_t o = (((size_t)(b * H_ + h) * S_ + s) << 6) + d;
                        *(bf162*)&oh[o] = __halves2bfloat162(h0, h1);
                        *(bf162*)&ol[o] = __halves2bfloat162(l0, l1);
                    } else {
                        size_t base = (size_t)(b * H_ + h) * DH_;
                        g_Vt_hi[(base + d) * S_ + s] = h0;
                        g_Vt_hi[(base + d + 1) * S_ + s] = h1;
                        g_Vt_lo[(base + d) * S_ + s] = l0;
                        g_Vt_lo[(base + d + 1) * S_ + s] = l1;
                    }
                } else if (MODE == 1) {
                    *(float2*)&out[(size_t)m * 512 + n] =
                        make_float2(v0 + bias[n], v1 + bias[n + 1]);
                } else {  // MODE 2
                    int h = bz & 7;
                    float tb = tbias[h];
                    size_t mn = (size_t)m * S_ + n;
                    float2 tw = *(const float2*)&g_tw[mn];
                    int2 mk = *(const int2*)&mask[mn];
                    float s0 = v0 * SCALE_ + tb * tw.x;
                    float s1 = v1 * SCALE_ + tb * tw.y;
                    if (mk.x == 0) s0 = -1e9f;
                    if (mk.y == 0) s1 = -1e9f;
                    *(float2*)&out[(size_t)bz * S_ * S_ + mn] = make_float2(s0, s1);
                    acc[mf][nf][2 * hh] = s0;
                    acc[mf][nf][2 * hh + 1] = s1;
                }
            }
        }
    }

    if (MODE == 2) {
        #pragma unroll
        for (int mf = 0; mf < 4; mf++) {
            #pragma unroll
            for (int hh = 0; hh < 2; hh++) {
                float mx = -INFINITY;
                #pragma unroll
                for (int nf = 0; nf < 4; nf++)
                    mx = fmaxf(mx, fmaxf(acc[mf][nf][2 * hh], acc[mf][nf][2 * hh + 1]));
                mx = fmaxf(mx, __shfl_xor_sync(0xffffffffu, mx, 1));
                mx = fmaxf(mx, __shfl_xor_sync(0xffffffffu, mx, 2));
                if ((lane & 3) == 0)
                    red_s[wn * 128 + wm * 64 + mf * 16 + lrow + hh * 8] = mx;
            }
        }
        __syncthreads();
        if (tid < 128) {
            float mx = red_s[tid];
            #pragma unroll
            for (int w = 1; w < 4; w++) mx = fmaxf(mx, red_s[w * 128 + tid]);
            rowm_s[tid] = mx;
        }
        __syncthreads();
        #pragma unroll
        for (int mf = 0; mf < 4; mf++) {
            #pragma unroll
            for (int hh = 0; hh < 2; hh++) {
                int row = wm * 64 + mf * 16 + lrow + hh * 8;
                float rm = rowm_s[row];
                float sm = 0.f;
                #pragma unroll
                for (int nf = 0; nf < 4; nf++)
                    sm += __expf(acc[mf][nf][2 * hh] - rm) +
                          __expf(acc[mf][nf][2 * hh + 1] - rm);
                sm += __shfl_xor_sync(0xffffffffu, sm, 1);
                sm += __shfl_xor_sync(0xffffffffu, sm, 2);
                if ((lane & 3) == 0) red_s[wn * 128 + row] = sm;
            }
        }
        __syncthreads();
        if (tid < 128) {
            float l = red_s[tid];
            #pragma unroll
            for (int w = 1; w < 4; w++) l += red_s[w * 128 + tid];
            size_t o = ((size_t)bz * 16 + blockIdx.x) * S_ + m0 + tid;
            g_pm[o] = rowm_s[tid];
            g_pl[o] = l;
        }
    }
}

// ---------------------------------------------------------------------------
__global__ void combine_kernel() {
    int idx = blockIdx.x * 256 + threadIdx.x;
    int bz = idx >> 11, r = idx & 2047;
    float mt[16];
    float mx = -INFINITY;
    #pragma unroll
    for (int t = 0; t < 16; t++) {
        mt[t] = g_pm[((size_t)bz * 16 + t) * S_ + r];
        mx = fmaxf(mx, mt[t]);
    }
    float l = 0.f;
    #pragma unroll
    for (int t = 0; t < 16; t++)
        l += g_pl[((size_t)bz * 16 + t) * S_ + r] * __expf(mt[t] - mx);
    g_m[idx] = mx;
    g_linv[idx] = 1.0f / l;
}

// ---------------------------------------------------------------------------
// ctx: raw s -> softmax finalize -> fp32 P (mandatory) -> P.V (3xBF16 MMA).
// BK=32 per iter (64 iters), 3-stage cp.async. 256 thr: wm=wid%4, wn=wid/4.
// Dynamic smem layout:
//   [0, 55296)        sS: 3 stages x 128 rows x 36 floats (s chunk)
//   [55296, 82944)    sV: 3 stages x 64 rows x 72 bf16 ([hi32|lo32|pad8])
//   [82944, 101376)   sP: 128 rows x 72 bf16
//   [101376, 102400)  sm_m[128], sm_li[128]
// ---------------------------------------------------------------------------
__global__ __launch_bounds__(256) void ctx_kernel(float* __restrict__ P) {
    extern __shared__ char smraw[];
    float* sm_m  = (float*)(smraw + 101376);
    float* sm_li = (float*)(smraw + 101888);

    const int tid = threadIdx.x, wid = tid >> 5, lane = tid & 31;
    const int wm = wid & 3, wn = wid >> 2;
    const int bz = blockIdx.z;
    const int b = bz >> 3, h = bz & 7;
    const int m0 = blockIdx.y * 128;

    float* Pbh = P + (size_t)bz * S_ * S_;
    const bf16* Vh0 = g_Vt_hi + (size_t)bz * DH_ * S_;
    const bf16* Vl0 = g_Vt_lo + (size_t)bz * DH_ * S_;

    if (tid < 128) {
        sm_m[tid]  = g_m[bz * S_ + m0 + tid];
        sm_li[tid] = g_linv[bz * S_ + m0 + tid];
    }

    float acc[2][4][4];
    #pragma unroll
    for (int i = 0; i < 2; i++)
        #pragma unroll
        for (int j = 0; j < 4; j++)
            #pragma unroll
            for (int q = 0; q < 4; q++) acc[i][j][q] = 0.f;

    const uint32_t sbase = (uint32_t)__cvta_generic_to_shared(smraw);
    const uint32_t uP = sbase + 82944;
    const int t8 = lane >> 3, r8 = lane & 7;
    const int frow = r8 + 8 * (t8 & 1), fcol = 8 * (t8 >> 1);
    const int lrow = lane >> 2, lcol = (lane & 3) * 2;

    auto loadS = [&](int it, int slot) {
        uint32_t dstb = sbase + slot * 18432;
        #pragma unroll
        for (int i = 0; i < 4; i++) {
            int idx = tid + i * 256;
            int r = idx >> 3, c = (idx & 7) * 4;
            cpa16(dstb + (r * 36 + c) * 4, Pbh + (size_t)(m0 + r) * S_ + it * 32 + c);
        }
    };
    auto loadV = [&](int it, int slot) {
        uint32_t dstb = sbase + 55296 + slot * 9216;
        #pragma unroll
        for (int i = 0; i < 2; i++) {
            int idx = tid + i * 256;
            int r = idx >> 3, c = idx & 7;
            const bf16* src = ((c < 4) ? Vh0 : Vl0) + (size_t)r * S_ + it * 32 + (c & 3) * 8;
            cpa16(dstb + (r * 72 + ((c < 4) ? 0 : 32) + (c & 3) * 8) * 2, src);
        }
    };

    loadS(0, 0); loadV(0, 0); cp_commit();
    loadS(1, 1); loadV(1, 1); cp_commit();

    const int cr = tid >> 1, cb = (tid & 1) * 16;
    for (int it = 0; it < 64; it++) {
        cp_wait<1>();
        __syncthreads();

        // finalize p = exp(s - m) * linv, write fp32 P, split into sP
        {
            const float* ss = (const float*)(smraw + (it % 3) * 18432) + cr * 36 + cb;
            float mrow = sm_m[cr], li = sm_li[cr];
            float p[16];
            #pragma unroll
            for (int i = 0; i < 16; i += 4) {
                float4 a = *(const float4*)(ss + i);
                p[i]     = __expf(a.x - mrow) * li;
                p[i + 1] = __expf(a.y - mrow) * li;
                p[i + 2] = __expf(a.z - mrow) * li;
                p[i + 3] = __expf(a.w - mrow) * li;
            }
            float* gdst = Pbh + (size_t)(m0 + cr) * S_ + it * 32 + cb;
            #pragma unroll
            for (int i = 0; i < 16; i += 4)
                *(float4*)(gdst + i) = make_float4(p[i], p[i + 1], p[i + 2], p[i + 3]);
            bf16* sp = (bf16*)(smraw + 82944) + cr * 72;
            #pragma unroll
            for (int i = 0; i < 16; i += 8) {
                uint4 hv, lv;
                #pragma unroll
                for (int j = 0; j < 8; j += 2) {
                    bf16 a0 = __float2bfloat16(p[i + j]);
                    bf16 a1 = __float2bfloat16(p[i + j + 1]);
                    ((bf162*)&hv)[j >> 1] = __halves2bfloat162(a0, a1);
                    ((bf162*)&lv)[j >> 1] = __halves2bfloat162(
                        __float2bfloat16(p[i + j] - __bfloat162float(a0)),
                        __float2bfloat16(p[i + j + 1] - __bfloat162float(a1)));
                }
                *(uint4*)(sp + cb + i) = hv;
                *(uint4*)(sp + 32 + cb + i) = lv;
            }
        }
        __syncthreads();

        const uint32_t sVt = sbase + 55296 + (it % 3) * 9216;
        #pragma unroll
        for (int p3 = 0; p3 < 3; p3++) {
            const int ao = (p3 == 2) ? 32 : 0;
            const int bo = (p3 == 1) ? 32 : 0;
            #pragma unroll
            for (int ks = 0; ks < 32; ks += 16) {
                uint32_t af[2][4], bfr[4][2];
                #pragma unroll
                for (int mf = 0; mf < 2; mf++)
                    ldsm4(uP + ((wm * 32 + mf * 16 + frow) * 72 + ao + ks + fcol) * 2,
                          af[mf][0], af[mf][1], af[mf][2], af[mf][3]);
                #pragma unroll
                for (int nf2 = 0; nf2 < 2; nf2++) {
                    uint32_t r0, r1, r2, r3;
                    ldsm4(sVt + ((wn * 32 + nf2 * 16 + frow) * 72 + bo + ks + fcol) * 2,
                          r0, r1, r2, r3);
                    bfr[2 * nf2][0] = r0;      bfr[2 * nf2][1] = r2;
                    bfr[2 * nf2 + 1][0] = r1;  bfr[2 * nf2 + 1][1] = r3;
                }
                #pragma unroll
                for (int mf = 0; mf < 2; mf++)
                    #pragma unroll
                    for (int nf = 0; nf < 4; nf++)
                        mma16816(acc[mf][nf], af[mf], bfr[nf]);
            }
        }

        // prefetch into slot freed two iterations ago (safe: two barriers since)
        if (it + 2 < 64) { loadS(it + 2, (it + 2) % 3); loadV(it + 2, (it + 2) % 3); }
        cp_commit();
    }

    #pragma unroll
    for (int mf = 0; mf < 2; mf++) {
        #pragma unroll
        for (int nf = 0; nf < 4; nf++) {
            #pragma unroll
            for (int hh = 0; hh < 2; hh++) {
                int m = m0 + wm * 32 + mf * 16 + lrow + hh * 8;
                int d = wn * 32 + nf * 8 + lcol;
                size_t o = ((size_t)b * S_ + m) * E_ + h * DH_ + d;
                float v0 = acc[mf][nf][2 * hh], v1 = acc[mf][nf][2 * hh + 1];
                bf16 h0 = __float2bfloat16(v0), h1 = __float2bfloat16(v1);
                *(bf162*)&g_C_hi[o] = __halves2bfloat162(h0, h1);
                *(bf162*)&g_C_lo[o] = __halves2bfloat162(
                    __float2bfloat16(v0 - __bfloat162float(h0)),
                    __float2bfloat16(v1 - __bfloat162float(h1)));
            }
        }
    }
}

// ---------------------------------------------------------------------------
extern "C" void kernel_launch(void* const* d_in, const int* in_sizes, int n_in,
                              void* d_out, int out_size) {
    const float* query = (const float*)d_in[0];
    const float* key   = (const float*)d_in[1];
    const float* value = (const float*)d_in[2];
    const int*   tmask = (const int*)d_in[3];
    const float* ldist = (const float*)d_in[4];
    const float* Wq = (const float*)d_in[5];
    const float* bq = (const float*)d_in[6];
    const float* Wk = (const float*)d_in[7];
    const float* bk = (const float*)d_in[8];
    const float* Wv = (const float*)d_in[9];
    const float* bv = (const float*)d_in[10];
    const float* Wo = (const float*)d_in[11];
    const float* bo = (const float*)d_in[12];
    const float* tbias = (const float*)d_in[13];

    float* out_attn  = (float*)d_out;
    float* out_probs = (float*)d_out + (size_t)B_ * S_ * E_;

    static int configured = 0;
    if (!configured) {
        cudaFuncSetAttribute(k_mm<5>, cudaFuncAttributeMaxDynamicSharedMemorySize, 84480);
        cudaFuncSetAttribute(k_mm<2>, cudaFuncAttributeMaxDynamicSharedMemorySize, 84480);
        cudaFuncSetAttribute(k_mm<1>, cudaFuncAttributeMaxDynamicSharedMemorySize, 84480);
        cudaFuncSetAttribute(ctx_kernel, cudaFuncAttributeMaxDynamicSharedMemorySize, 102400);
        configured = 1;
    }

    // preprocessing (3 launches)
    tw_kernel<<<4096, 256>>>(ldist);
    dim3 gi(2048, 1, 3);
    split_in_kernel<<<gi, 256>>>(query, key, value);
    dim3 gw(256, 1, 4);
    split_w_kernel<<<gw, 256>>>(Wq, Wk, Wv, Wo);

    // fused QKV projections
    dim3 gqkv(4, 32, 3);
    k_mm<5><<<gqkv, 256, 84480>>>(bq, bk, bv, nullptr, nullptr, nullptr);

    // scores (raw s + per-tile stats)
    dim3 gs(16, 16, 16);
    k_mm<2><<<gs, 256, 84480>>>(nullptr, nullptr, nullptr, out_probs, tmask, tbias);

    combine_kernel<<<128, 256>>>();

    // ctx: softmax finalize + P.V
    dim3 gc(1, 16, 16);
    ctx_kernel<<<gc, 256, 102400>>>(out_probs);

    // output projection
    dim3 gp(4, 32, 1);
    k_mm<1><<<gp, 256, 84480>>>(bo, nullptr, nullptr, out_attn, nullptr, nullptr);
}